// round 13
// baseline (speedup 1.0000x reference)
#include <cuda_runtime.h>
#include <cuda_bf16.h>

// Traffic model (pinned over R2-R8): 64B HBM atom ->
//   z_1  [B,16] fp32: need 20B of each 64B row, pay full row  = 256 MB
//   dir  [B,8]  fp32: one 4B gather/row, rows dense in 64B     = 128 MB
//   out  [B]    fp32                                           =  16 MB
// 400 MB floor; only lever is DRAM busy% (best so far 86.3%).
//
// This round: 2 rows/thread as SPLIT HALVES (t and t+n/2), not adjacent
// pairs. Every load stream keeps R2's exact warp coalescing (64B stride,
// 16 L1 wavefronts/instr — R8's adjacent pairing doubled this to 32),
// while front-batching 4 independent z loads + 2 independent gathers per
// thread (2x R2's MLP). __ldg + plain multi-wave launch (empirically best),
// regs pinned via __launch_bounds__(256,8) for full 2048 thr/SM residency.

__device__ __forceinline__ int zone_of(float lx, float ly, float rx, float ry)
{
    float dx = rx - lx;
    float dy = -(ry - ly);
    float phi = atan2f(dy, dx) * 57.29577951308232f;
    if (phi < 0.0f) phi += 360.0f;
    int pcs = (90 + (int)phi) % 360;    // truncation == floor (phi >= 0)
    return ((pcs + 11) / 22) & 7;       // area_angle=22, half=11 (exact)
}

__global__ __launch_bounds__(256, 8) void slope_valuation_kernel(
    const float4* __restrict__ z4,   // z_1 as float4 (4 per 16-float row)
    const float*  __restrict__ z,    // z_1 scalar view
    const float*  __restrict__ dir,  // [B, 8]
    float*        __restrict__ out,  // [B]
    int n2)                          // n/2
{
    int t = blockIdx.x * blockDim.x + threadIdx.x;
    if (t >= n2) return;

    size_t r0 = (size_t)t;           // first half
    size_t r1 = (size_t)t + n2;      // second half

    // 4 independent front-batched z loads; each stream coalesces like R2
    float4 va  = __ldg(&z4[r0 * 4]);        // line, lx, ly, rx
    float  rya = __ldg(&z[r0 * 16 + 4]);    // ry (same 32B sector)
    float4 vb  = __ldg(&z4[r1 * 4]);
    float  ryb = __ldg(&z[r1 * 16 + 4]);

    int za = zone_of(va.y, va.z, va.w, rya);
    int zb = zone_of(vb.y, vb.z, vb.w, ryb);

    // two independent gathers; each a coalesced row-sequential stream
    float pa = __ldg(&dir[r0 * 8 + za]);
    float pb = __ldg(&dir[r1 * 8 + zb]);

    out[r0] = (va.x != 0.0f) ? pa : 0.0f;
    out[r1] = (vb.x != 0.0f) ? pb : 0.0f;
}

// Tail for odd n (not hit at B = 4M)
__global__ void slope_valuation_tail(
    const float4* __restrict__ z4, const float* __restrict__ z,
    const float*  __restrict__ dir, float* __restrict__ out, int i)
{
    float4 v  = __ldg(&z4[(size_t)i * 4]);
    float  ry = __ldg(&z[(size_t)i * 16 + 4]);
    int    zn = zone_of(v.y, v.z, v.w, ry);
    float  p  = __ldg(&dir[(size_t)i * 8 + zn]);
    out[i] = (v.x != 0.0f) ? p : 0.0f;
}

extern "C" void kernel_launch(void* const* d_in, const int* in_sizes, int n_in,
                              void* d_out, int out_size)
{
    const float* z_1 = (const float*)d_in[0];   // [B,16] fp32
    const float* dir = (const float*)d_in[1];   // [B,8]  fp32
    float* out = (float*)d_out;                 // [B]    fp32

    int n  = in_sizes[0] / 16;                  // B rows
    int n2 = n / 2;

    int threads = 256;
    int blocks = (n2 + threads - 1) / threads;
    slope_valuation_kernel<<<blocks, threads>>>(
        (const float4*)z_1, z_1, dir, out, n2);

    if (n & 1) {
        slope_valuation_tail<<<1, 1>>>(
            (const float4*)z_1, z_1, dir, out, n - 1);
    }
}

// round 15
// speedup vs baseline: 1.0073x; 1.0073x over previous
#include <cuda_runtime.h>
#include <cuda_bf16.h>

// R2 body (best of 6 variants: 58.56us kernel, DRAM 86.3%, 400 MB traffic
// floor) + ONE new mechanism: L2 prefetch of the dir row, issued up front.
//
// The dependent gather dir[i*8+zone] was a DRAM miss (~577cyc) serialized
// behind the z load + atan2 chain. prefetch.global.L2 on the row base is
// fire-and-forget: it moves the line DRAM->L2 concurrently with the z load
// (full MLP, no registers, no L1 data return), so the later gather is an
// L2 hit (~250cyc). Same DRAM traffic, shorter serialized tail per thread.
// Unlike the failed R3/R4 full-row data preload, this adds no L1 wavefronts
// and no select tree.
//
// z_1 [B,16] fp32: float4 @ row base (cols 0-3) + scalar col 4, one 32B
// sector; DRAM fetches the 64B row regardless (granule measured in R2).

__global__ __launch_bounds__(256) void slope_valuation_kernel(
    const float4* __restrict__ z4,   // z_1 as float4 (4 per 16-float row)
    const float*  __restrict__ z,    // z_1 scalar view
    const float*  __restrict__ dir,  // [B, 8]
    float*        __restrict__ out,  // [B]
    int n)
{
    int i = blockIdx.x * blockDim.x + threadIdx.x;
    if (i >= n) return;

    const float* dir_row = dir + (size_t)i * 8;

    // Fire-and-forget: pull the dir row into L2 while the z load is in flight.
    asm volatile("prefetch.global.L2 [%0];" :: "l"(dir_row));

    // One 16B load covering cols 0..3 (line, lx, ly, rx)
    float4 v = __ldg(&z4[(size_t)i * 4]);
    // col 4 (ry), same 32B sector as the float4
    float ry = __ldg(&z[(size_t)i * 16 + 4]);

    float dx = v.w - v.y;
    float dy = -(ry - v.z);

    float phi = atan2f(dy, dx) * 57.29577951308232f;
    if (phi < 0.0f) phi += 360.0f;

    int pcs  = (90 + (int)phi) % 360;   // truncation == floor (phi >= 0)
    int zone = ((pcs + 11) / 22) & 7;   // area_angle=22, half=11 (exact)

    float picked = __ldg(&dir_row[zone]);   // now an L2 hit
    out[i] = (v.x != 0.0f) ? picked : 0.0f;
}

extern "C" void kernel_launch(void* const* d_in, const int* in_sizes, int n_in,
                              void* d_out, int out_size)
{
    const float* z_1 = (const float*)d_in[0];   // [B,16] fp32
    const float* dir = (const float*)d_in[1];   // [B,8]  fp32
    float* out = (float*)d_out;                 // [B]    fp32

    int n = in_sizes[0] / 16;                   // B rows

    int threads = 256;
    int blocks = (n + threads - 1) / threads;
    slope_valuation_kernel<<<blocks, threads>>>(
        (const float4*)z_1, z_1, dir, out, n);
}

// round 16
// speedup vs baseline: 1.0200x; 1.0127x over previous
#include <cuda_runtime.h>
#include <cuda_bf16.h>

// Final-form candidate. Body = R15 (best: 58.46us kernel, DRAM 86.4%,
// 6844 GB/s on the measured 400 MB traffic floor).
//
// Model conclusion after 7 variants (84-86.4% DRAM busy band): busy% ==
// delivered/spec -> the HBM controller is at its efficiency limit for this
// mix (half-sector z reads + dense dir reads + 4% write stream). Remaining
// tweaks are launch shape + dependent-chain trims:
//   - block 512 (4 CTAs/SM, same 2048 resident threads; only untested shape)
//   - (90+int(phi)) % 360 -> conditional subtract (pcs in [90,450))
//   - keep fire-and-forget L2 prefetch of the dir row (neutral-positive)

__global__ __launch_bounds__(512) void slope_valuation_kernel(
    const float4* __restrict__ z4,   // z_1 as float4 (4 per 16-float row)
    const float*  __restrict__ z,    // z_1 scalar view
    const float*  __restrict__ dir,  // [B, 8]
    float*        __restrict__ out,  // [B]
    int n)
{
    int i = blockIdx.x * blockDim.x + threadIdx.x;
    if (i >= n) return;

    const float* dir_row = dir + (size_t)i * 8;

    // Pull the dir line DRAM->L2 while the z load is in flight (no reg dep).
    asm volatile("prefetch.global.L2 [%0];" :: "l"(dir_row));

    // cols 0..3 (line, lx, ly, rx): one 16B load at row base
    float4 v = __ldg(&z4[(size_t)i * 4]);
    // col 4 (ry): same 32B sector
    float ry = __ldg(&z[(size_t)i * 16 + 4]);

    float dx = v.w - v.y;
    float dy = -(ry - v.z);

    float phi = atan2f(dy, dx) * 57.29577951308232f;
    if (phi < 0.0f) phi += 360.0f;

    // pcs = (90 + int(phi)) % 360 ; int(phi) in [0,360) -> single cond-sub
    int pcs = 90 + (int)phi;
    if (pcs >= 360) pcs -= 360;

    int zone = ((pcs + 11) / 22) & 7;   // area_angle=22, half=11 (exact)

    float picked = __ldg(&dir_row[zone]);   // L2 hit after prefetch
    out[i] = (v.x != 0.0f) ? picked : 0.0f;
}

extern "C" void kernel_launch(void* const* d_in, const int* in_sizes, int n_in,
                              void* d_out, int out_size)
{
    const float* z_1 = (const float*)d_in[0];   // [B,16] fp32
    const float* dir = (const float*)d_in[1];   // [B,8]  fp32
    float* out = (float*)d_out;                 // [B]    fp32

    int n = in_sizes[0] / 16;                   // B rows

    int threads = 512;
    int blocks = (n + threads - 1) / threads;
    slope_valuation_kernel<<<blocks, threads>>>(
        (const float4*)z_1, z_1, dir, out, n);
}